// round 14
// baseline (speedup 1.0000x reference)
#include <cuda_runtime.h>
#include <cuda_fp16.h>
#include <cstdint>
#include <cstddef>
#include <cstring>

#define BATCH 1024
#define DIM   1024
#define HID   4096
#define TSTEPS 16
#define BD (BATCH*DIM)

__device__ __half g_W1[(size_t)HID * DIM];   // W1^T fp16 [4096,1024]
__device__ __half g_W2[(size_t)DIM * HID];   // W2^T fp16 [1024,4096]
__device__ __half g_H[(size_t)BATCH * HID];  // hidden fp16
__device__ __half g_Yh[BD];                  // state fp16 (rounded)
__device__ float  g_Yacc[BD];                // RK4 accumulator (fp32)
__device__ float  g_P[(size_t)4 * BD];       // split-K partials
__device__ int    g_cnt[64];                 // per-tile completion counters (zero-init)

__device__ __forceinline__ uint32_t h2_bits(__half2 v) {
    uint32_t u;
    memcpy(&u, &v, 4);
    return u;
}
__device__ __forceinline__ uint32_t smem_u32(const void* p) {
    uint32_t a;
    asm("{ .reg .u64 t; cvta.to.shared.u64 t, %1; cvt.u32.u64 %0, t; }" : "=r"(a) : "l"(p));
    return a;
}
__device__ __forceinline__ void cpa16(uint32_t s, const void* g) {
    asm volatile("cp.async.cg.shared.global [%0], [%1], 16;"
                 :: "r"(s), "l"(__cvta_generic_to_global(g)));
}
#define CP_COMMIT() asm volatile("cp.async.commit_group;" ::: "memory")
#define CP_WAIT0()  asm volatile("cp.async.wait_group 0;" ::: "memory")
#define CP_WAIT1()  asm volatile("cp.async.wait_group 1;" ::: "memory")

__device__ __forceinline__ void ldsm4(uint32_t* r, uint32_t addr) {
    asm volatile("ldmatrix.sync.aligned.m8n8.x4.shared.b16 {%0,%1,%2,%3}, [%4];"
                 : "=r"(r[0]), "=r"(r[1]), "=r"(r[2]), "=r"(r[3]) : "r"(addr));
}
__device__ __forceinline__ void mma_f16(float* d, const uint32_t* a, const uint32_t* b) {
    asm volatile(
        "mma.sync.aligned.m16n8k16.row.col.f32.f16.f16.f32 "
        "{%0,%1,%2,%3}, {%4,%5,%6,%7}, {%8,%9}, {%0,%1,%2,%3};"
        : "+f"(d[0]), "+f"(d[1]), "+f"(d[2]), "+f"(d[3])
        : "r"(a[0]), "r"(a[1]), "r"(a[2]), "r"(a[3]), "r"(b[0]), "r"(b[1]));
}
__device__ __forceinline__ float tanh_fast(float x) {
    asm("tanh.approx.f32 %0, %0;" : "+f"(x));
    return x;
}

// ======== GEMM1: H = tanh(Y @ W1^T + b1) ========
// 128x128 tile, 128 thr = 4 warps (2Mx2N), warp 64x64, 2 CTAs/SM,
// 3-stage smem ring + fragment double-buffer with boundary hiding (R13).
__global__ void __launch_bounds__(128, 2)
hgemm1(const __half* __restrict__ A, const __half* __restrict__ B,
       const float* __restrict__ bias, __half* __restrict__ H) {
    constexpr int APLANE = 128 * 128;
    constexpr int STAGE = 2 * APLANE;
    constexpr int K = 1024, NC = 16;
    extern __shared__ char smem[];
    const uint32_t sb0 = smem_u32(smem);

    const int tid = threadIdx.x;
    const int wid = tid >> 5, lane = tid & 31;
    const int wm = wid & 1, wn = wid >> 1;
    const int gid = lane >> 2, tig = lane & 3;
    const int rowBase = blockIdx.y * 128;
    const int colBase = blockIdx.x * 128;

    auto load_stage = [&](int kc, int st) {
        const uint32_t sb = sb0 + st * STAGE;
        const size_t keB = (size_t)kc * 128;
#pragma unroll
        for (int c = tid; c < 128 * 8; c += 128) {
            const int row = c >> 3, kb = (c & 7) << 4;
            const uint32_t so = row * 128 + (kb ^ ((row & 7) << 4));
            cpa16(sb + so, (const char*)A + (size_t)(rowBase + row) * (K * 2) + keB + kb);
            cpa16(sb + APLANE + so,
                  (const char*)B + (size_t)(colBase + row) * (K * 2) + keB + kb);
        }
    };

    const int arow = wm * 64 + (lane & 15);
    const int akb = (lane >> 4) << 4;
    const int brow = wn * 64 + ((lane >> 4) << 3) + (lane & 7);
    const int bkb = (((lane >> 3) & 1)) << 4;

    auto lda = [&](uint32_t* af, uint32_t sb, int t) {
#pragma unroll
        for (int mi = 0; mi < 4; ++mi) {
            const int r = arow + mi * 16;
            ldsm4(af + mi * 4, sb + r * 128 + ((t * 32 + akb) ^ ((r & 7) << 4)));
        }
    };
    auto ldb = [&](uint32_t* bf, uint32_t sb, int t) {
#pragma unroll
        for (int bi = 0; bi < 4; ++bi) {
            const int r = brow + bi * 16;
            ldsm4(bf + bi * 4,
                  sb + APLANE + r * 128 + ((t * 32 + bkb) ^ ((r & 7) << 4)));
        }
    };

    float acc[4][8][4];
#pragma unroll
    for (int i = 0; i < 4; ++i)
#pragma unroll
        for (int j = 0; j < 8; ++j)
#pragma unroll
            for (int e = 0; e < 4; ++e) acc[i][j][e] = 0.f;

    load_stage(0, 0);
    CP_COMMIT();
    load_stage(1, 1);
    CP_COMMIT();
    CP_WAIT1();
    __syncthreads();

    uint32_t af[2][16], bf[2][16];
    lda(af[0], sb0, 0);
    ldb(bf[0], sb0, 0);

    for (int kc = 0; kc < NC; ++kc) {
        __syncthreads();
        if (kc + 2 < NC) {
            load_stage(kc + 2, (kc + 2) % 3);
            CP_COMMIT();
        }
        const uint32_t sb = sb0 + (kc % 3) * STAGE;
        const uint32_t sbn = sb0 + ((kc + 1) % 3) * STAGE;
#pragma unroll
        for (int t = 0; t < 4; ++t) {
            const int cur = t & 1, nxt = cur ^ 1;
            if (t < 3) {
                lda(af[nxt], sb, t + 1);
                ldb(bf[nxt], sb, t + 1);
            } else if (kc + 1 < NC) {
                if (kc + 2 < NC) { CP_WAIT1(); } else { CP_WAIT0(); }
                lda(af[nxt], sbn, 0);
                ldb(bf[nxt], sbn, 0);
            }
#pragma unroll
            for (int mi = 0; mi < 4; ++mi)
#pragma unroll
                for (int ni = 0; ni < 8; ++ni)
                    mma_f16(acc[mi][ni], &af[cur][mi * 4], &bf[cur][ni * 2]);
        }
    }

#pragma unroll
    for (int mi = 0; mi < 4; ++mi) {
#pragma unroll
        for (int ni = 0; ni < 8; ++ni) {
            const int col = colBase + wn * 64 + ni * 8 + tig * 2;
            const float2 bb = *reinterpret_cast<const float2*>(bias + col);
#pragma unroll
            for (int hf = 0; hf < 2; ++hf) {
                const int row = rowBase + wm * 64 + mi * 16 + gid + hf * 8;
                const float v0 = tanh_fast(acc[mi][ni][hf * 2 + 0] + bb.x);
                const float v1 = tanh_fast(acc[mi][ni][hf * 2 + 1] + bb.y);
                *reinterpret_cast<__half2*>(H + (size_t)row * HID + col) =
                    __floats2half2_rn(v0, v1);
            }
        }
    }
}

// ======== GEMM2 (split-K x4) + FUSED reduce + RK4 stage update ========
// Each z-CTA stores its partial plane; the last CTA per tile (threadfence +
// counter) reduces in FRAGMENT layout (own partial still in regs, 3 planes
// from L2) and applies the RK4 update. No separate kreduce kernel.
template <int EPI>
__global__ void __launch_bounds__(128, 2)
hgemm2(const __half* __restrict__ A, const __half* __restrict__ B,
       float* __restrict__ P, const float* __restrict__ b2,
       const float* __restrict__ ybase, float* __restrict__ Yacc,
       float* __restrict__ yout, __half* __restrict__ Yh,
       const float* __restrict__ tspan, int step) {
    constexpr int APLANE = 128 * 128;
    constexpr int STAGE = 2 * APLANE;
    constexpr int K = 4096, NC = 16;
    extern __shared__ char smem[];
    const uint32_t sb0 = smem_u32(smem);

    const int tid = threadIdx.x;
    const int wid = tid >> 5, lane = tid & 31;
    const int wm = wid & 1, wn = wid >> 1;
    const int gid = lane >> 2, tig = lane & 3;
    const int rowBase = blockIdx.y * 128;
    const int colBase = blockIdx.x * 128;
    const int myz = blockIdx.z;
    const size_t kzB = (size_t)myz * 2048;

    auto load_stage = [&](int kc, int st) {
        const uint32_t sb = sb0 + st * STAGE;
        const size_t keB = kzB + (size_t)kc * 128;
#pragma unroll
        for (int c = tid; c < 128 * 8; c += 128) {
            const int row = c >> 3, kb = (c & 7) << 4;
            const uint32_t so = row * 128 + (kb ^ ((row & 7) << 4));
            cpa16(sb + so, (const char*)A + (size_t)(rowBase + row) * (K * 2) + keB + kb);
            cpa16(sb + APLANE + so,
                  (const char*)B + (size_t)(colBase + row) * (K * 2) + keB + kb);
        }
    };

    const int arow = wm * 64 + (lane & 15);
    const int akb = (lane >> 4) << 4;
    const int brow = wn * 64 + ((lane >> 4) << 3) + (lane & 7);
    const int bkb = (((lane >> 3) & 1)) << 4;

    auto lda = [&](uint32_t* af, uint32_t sb, int t) {
#pragma unroll
        for (int mi = 0; mi < 4; ++mi) {
            const int r = arow + mi * 16;
            ldsm4(af + mi * 4, sb + r * 128 + ((t * 32 + akb) ^ ((r & 7) << 4)));
        }
    };
    auto ldb = [&](uint32_t* bf, uint32_t sb, int t) {
#pragma unroll
        for (int bi = 0; bi < 4; ++bi) {
            const int r = brow + bi * 16;
            ldsm4(bf + bi * 4,
                  sb + APLANE + r * 128 + ((t * 32 + bkb) ^ ((r & 7) << 4)));
        }
    };

    float acc[4][8][4];
#pragma unroll
    for (int i = 0; i < 4; ++i)
#pragma unroll
        for (int j = 0; j < 8; ++j)
#pragma unroll
            for (int e = 0; e < 4; ++e) acc[i][j][e] = 0.f;

    load_stage(0, 0);
    CP_COMMIT();
    load_stage(1, 1);
    CP_COMMIT();
    CP_WAIT1();
    __syncthreads();

    uint32_t af[2][16], bf[2][16];
    lda(af[0], sb0, 0);
    ldb(bf[0], sb0, 0);

    for (int kc = 0; kc < NC; ++kc) {
        __syncthreads();
        if (kc + 2 < NC) {
            load_stage(kc + 2, (kc + 2) % 3);
            CP_COMMIT();
        }
        const uint32_t sb = sb0 + (kc % 3) * STAGE;
        const uint32_t sbn = sb0 + ((kc + 1) % 3) * STAGE;
#pragma unroll
        for (int t = 0; t < 4; ++t) {
            const int cur = t & 1, nxt = cur ^ 1;
            if (t < 3) {
                lda(af[nxt], sb, t + 1);
                ldb(bf[nxt], sb, t + 1);
            } else if (kc + 1 < NC) {
                if (kc + 2 < NC) { CP_WAIT1(); } else { CP_WAIT0(); }
                lda(af[nxt], sbn, 0);
                ldb(bf[nxt], sbn, 0);
            }
#pragma unroll
            for (int mi = 0; mi < 4; ++mi)
#pragma unroll
                for (int ni = 0; ni < 8; ++ni)
                    mma_f16(acc[mi][ni], &af[cur][mi * 4], &bf[cur][ni * 2]);
        }
    }

    // store own partial plane
    float* Pz = P + (size_t)myz * BD;
#pragma unroll
    for (int mi = 0; mi < 4; ++mi) {
#pragma unroll
        for (int ni = 0; ni < 8; ++ni) {
            const int col = colBase + wn * 64 + ni * 8 + tig * 2;
#pragma unroll
            for (int hf = 0; hf < 2; ++hf) {
                const int row = rowBase + wm * 64 + mi * 16 + gid + hf * 8;
                float2 v;
                v.x = acc[mi][ni][hf * 2 + 0];
                v.y = acc[mi][ni][hf * 2 + 1];
                *reinterpret_cast<float2*>(Pz + (size_t)row * DIM + col) = v;
            }
        }
    }

    // completion protocol: last CTA per (by,bx) tile reduces
    __shared__ int isLastS;
    __threadfence();
    __syncthreads();
    if (tid == 0) {
        const int ci = blockIdx.y * 8 + blockIdx.x;
        const int old = atomicAdd(&g_cnt[ci], 1);
        isLastS = (old == 3);
        if (old == 3) g_cnt[ci] = 0;  // reset for next launch (graph-safe)
    }
    __syncthreads();
    if (!isLastS) return;
    __threadfence();

    // fused reduce (fragment layout; own plane from regs) + RK4 update
    const float h = tspan[step + 1] - tspan[step];
#pragma unroll
    for (int mi = 0; mi < 4; ++mi) {
#pragma unroll
        for (int ni = 0; ni < 8; ++ni) {
            const int col = colBase + wn * 64 + ni * 8 + tig * 2;
            const float2 bb = *reinterpret_cast<const float2*>(b2 + col);
#pragma unroll
            for (int hf = 0; hf < 2; ++hf) {
                const int row = rowBase + wm * 64 + mi * 16 + gid + hf * 8;
                const size_t ix = (size_t)row * DIM + col;
                float2 s;
                s.x = acc[mi][ni][hf * 2 + 0];
                s.y = acc[mi][ni][hf * 2 + 1];
#pragma unroll
                for (int z = 0; z < 4; ++z) {
                    if (z != myz) {
                        const float2 p =
                            *reinterpret_cast<const float2*>(P + (size_t)z * BD + ix);
                        s.x += p.x;
                        s.y += p.y;
                    }
                }
                s.x += bb.x;
                s.y += bb.y;

                float2 o;
                if (EPI == 4) {
                    const float2 aa = *reinterpret_cast<const float2*>(Yacc + ix);
                    o.x = fmaf(h * (1.f / 6.f), s.x, aa.x);
                    o.y = fmaf(h * (1.f / 6.f), s.y, aa.y);
                    *reinterpret_cast<float2*>(yout + ix) = o;
                } else {
                    const float2 yy = *reinterpret_cast<const float2*>(ybase + ix);
                    const float cy = (EPI == 3) ? 1.0f : 0.5f;
                    o.x = fmaf(cy * h, s.x, yy.x);
                    o.y = fmaf(cy * h, s.y, yy.y);
                    float2 aa;
                    if (EPI == 1) {
                        aa.x = fmaf(h * (1.f / 6.f), s.x, yy.x);
                        aa.y = fmaf(h * (1.f / 6.f), s.y, yy.y);
                    } else {
                        aa = *reinterpret_cast<const float2*>(Yacc + ix);
                        aa.x = fmaf(h * (1.f / 3.f), s.x, aa.x);
                        aa.y = fmaf(h * (1.f / 3.f), s.y, aa.y);
                    }
                    *reinterpret_cast<float2*>(Yacc + ix) = aa;
                }
                *reinterpret_cast<__half2*>(Yh + ix) = __floats2half2_rn(o.x, o.y);
            }
        }
    }
}

// fp32 [R,C] -> fp16 plane [C,R] (transpose + round)
__global__ void ktrans_h(const float* __restrict__ in, __half* __restrict__ oh,
                         int R, int C) {
    __shared__ float t[32][33];
    const int bx = blockIdx.x * 32;
    const int by = blockIdx.y * 32;
    for (int i = threadIdx.y; i < 32; i += 8)
        t[i][threadIdx.x] = in[(size_t)(by + i) * C + bx + threadIdx.x];
    __syncthreads();
    for (int i = threadIdx.y; i < 32; i += 8)
        oh[(size_t)(bx + i) * R + by + threadIdx.x] = __float2half(t[threadIdx.x][i]);
}

__global__ void ky(const float* __restrict__ in, __half* __restrict__ oh, int n) {
    int i = blockIdx.x * 256 + threadIdx.x;
    if (i < n) oh[i] = __float2half(in[i]);
}

extern "C" void kernel_launch(void* const* d_in, const int* in_sizes, int n_in,
                              void* d_out, int out_size) {
    const float* y_init = (const float*)d_in[0];
    const float* tspan = (const float*)d_in[1];
    const float* W1 = (const float*)d_in[2];
    const float* b1 = (const float*)d_in[3];
    const float* W2 = (const float*)d_in[4];
    const float* b2 = (const float*)d_in[5];
    float* out = (float*)d_out;

    __half *W1p, *W2p, *H, *Yh;
    float *Yacc, *P;
    cudaGetSymbolAddress((void**)&W1p, g_W1);
    cudaGetSymbolAddress((void**)&W2p, g_W2);
    cudaGetSymbolAddress((void**)&H, g_H);
    cudaGetSymbolAddress((void**)&Yh, g_Yh);
    cudaGetSymbolAddress((void**)&Yacc, g_Yacc);
    cudaGetSymbolAddress((void**)&P, g_P);

    const int SMEM = 3 * 2 * 128 * 128;  // 3 stages x 32 KB = 98304
    cudaFuncSetAttribute(hgemm1, cudaFuncAttributeMaxDynamicSharedMemorySize, SMEM);
    cudaFuncSetAttribute(hgemm2<1>, cudaFuncAttributeMaxDynamicSharedMemorySize, SMEM);
    cudaFuncSetAttribute(hgemm2<2>, cudaFuncAttributeMaxDynamicSharedMemorySize, SMEM);
    cudaFuncSetAttribute(hgemm2<3>, cudaFuncAttributeMaxDynamicSharedMemorySize, SMEM);
    cudaFuncSetAttribute(hgemm2<4>, cudaFuncAttributeMaxDynamicSharedMemorySize, SMEM);

    cudaMemcpyAsync(out, tspan, TSTEPS * sizeof(float), cudaMemcpyDeviceToDevice, 0);
    float* traj = out + TSTEPS;
    cudaMemcpyAsync(traj, y_init, (size_t)BD * sizeof(float), cudaMemcpyDeviceToDevice, 0);

    ktrans_h<<<dim3(HID / 32, DIM / 32), dim3(32, 8)>>>(W1, W1p, DIM, HID);
    ktrans_h<<<dim3(DIM / 32, HID / 32), dim3(32, 8)>>>(W2, W2p, HID, DIM);
    ky<<<BD / 256, 256>>>(y_init, Yh, BD);

    const dim3 g1(HID / 128, BATCH / 128);      // (32, 8) = 256 CTAs
    const dim3 g2(DIM / 128, BATCH / 128, 4);   // (8, 8, 4) = 256 CTAs

    for (int s = 0; s < TSTEPS - 1; ++s) {
        const float* y = traj + (size_t)s * BD;
        float* ynext = traj + (size_t)(s + 1) * BD;

        hgemm1<<<g1, 128, SMEM>>>(Yh, W1p, b1, H);
        hgemm2<1><<<g2, 128, SMEM>>>(H, W2p, P, b2, y, Yacc, nullptr, Yh, tspan, s);

        hgemm1<<<g1, 128, SMEM>>>(Yh, W1p, b1, H);
        hgemm2<2><<<g2, 128, SMEM>>>(H, W2p, P, b2, y, Yacc, nullptr, Yh, tspan, s);

        hgemm1<<<g1, 128, SMEM>>>(Yh, W1p, b1, H);
        hgemm2<3><<<g2, 128, SMEM>>>(H, W2p, P, b2, y, Yacc, nullptr, Yh, tspan, s);

        hgemm1<<<g1, 128, SMEM>>>(Yh, W1p, b1, H);
        hgemm2<4><<<g2, 128, SMEM>>>(H, W2p, P, b2, nullptr, Yacc, ynext, Yh, tspan, s);
    }
}

// round 15
// speedup vs baseline: 1.4060x; 1.4060x over previous
#include <cuda_runtime.h>
#include <cuda_fp16.h>
#include <cstdint>
#include <cstddef>
#include <cstring>

#define BATCH 1024
#define DIM   1024
#define HID   4096
#define TSTEPS 16
#define BD (BATCH*DIM)

__device__ __half g_W1[(size_t)HID * DIM];   // W1^T fp16 [4096,1024]
__device__ __half g_W2[(size_t)DIM * HID];   // W2^T fp16 [1024,4096]
__device__ __half g_H[(size_t)BATCH * HID];  // hidden fp16
__device__ __half g_Yh[BD];                  // state fp16 (rounded)
__device__ float  g_Yacc[BD];                // RK4 accumulator (fp32)
__device__ __half g_P[(size_t)4 * BD];       // split-K partials (fp16)

__device__ __forceinline__ uint32_t smem_u32(const void* p) {
    uint32_t a;
    asm("{ .reg .u64 t; cvta.to.shared.u64 t, %1; cvt.u32.u64 %0, t; }" : "=r"(a) : "l"(p));
    return a;
}
__device__ __forceinline__ void cpa16(uint32_t s, const void* g) {
    asm volatile("cp.async.cg.shared.global [%0], [%1], 16;"
                 :: "r"(s), "l"(__cvta_generic_to_global(g)));
}
#define CP_COMMIT() asm volatile("cp.async.commit_group;" ::: "memory")
#define CP_WAIT0()  asm volatile("cp.async.wait_group 0;" ::: "memory")
#define CP_WAIT1()  asm volatile("cp.async.wait_group 1;" ::: "memory")

__device__ __forceinline__ void ldsm4(uint32_t* r, uint32_t addr) {
    asm volatile("ldmatrix.sync.aligned.m8n8.x4.shared.b16 {%0,%1,%2,%3}, [%4];"
                 : "=r"(r[0]), "=r"(r[1]), "=r"(r[2]), "=r"(r[3]) : "r"(addr));
}
__device__ __forceinline__ void mma_f16(float* d, const uint32_t* a, const uint32_t* b) {
    asm volatile(
        "mma.sync.aligned.m16n8k16.row.col.f32.f16.f16.f32 "
        "{%0,%1,%2,%3}, {%4,%5,%6,%7}, {%8,%9}, {%0,%1,%2,%3};"
        : "+f"(d[0]), "+f"(d[1]), "+f"(d[2]), "+f"(d[3])
        : "r"(a[0]), "r"(a[1]), "r"(a[2]), "r"(a[3]), "r"(b[0]), "r"(b[1]));
}
__device__ __forceinline__ float tanh_fast(float x) {
    asm("tanh.approx.f32 %0, %0;" : "+f"(x));
    return x;
}

// Shared GEMM body (R13): C tile [128 x 128] of A[M,K] @ B[N,K]^T.
// 128 threads = 4 warps (2M x 2N), warp tile 64x64 (MI=4, NT=8). 2 CTAs/SM.
// 3-stage smem ring, loads 2 chunks ahead; next-chunk t0 fragments preloaded
// mid-chunk (no exposed smem-read latency at chunk boundaries).
// EPI=0: H = tanh(acc + bias) fp16 out.  EPI=1: P = acc fp16 out (split-K).
template <int EPI>
__device__ __forceinline__ void gemm_body(
    const __half* A, const __half* B, const float* bias, __half* H,
    __half* P, int K, size_t kzB, int NC, char* smem) {
    constexpr int APLANE = 128 * 128;   // 16 KB
    constexpr int STAGE = 2 * APLANE;   // 32 KB
    const uint32_t sb0 = smem_u32(smem);

    const int tid = threadIdx.x;
    const int wid = tid >> 5, lane = tid & 31;
    const int wm = wid & 1, wn = wid >> 1;
    const int gid = lane >> 2, tig = lane & 3;
    const int rowBase = blockIdx.y * 128;
    const int colBase = blockIdx.x * 128;

    auto load_stage = [&](int kc, int st) {
        const uint32_t sb = sb0 + st * STAGE;
        const size_t keB = kzB + (size_t)kc * 128;
#pragma unroll
        for (int c = tid; c < 128 * 8; c += 128) {
            const int row = c >> 3, kb = (c & 7) << 4;
            const uint32_t so = row * 128 + (kb ^ ((row & 7) << 4));
            cpa16(sb + so, (const char*)A + (size_t)(rowBase + row) * (K * 2) + keB + kb);
            cpa16(sb + APLANE + so,
                  (const char*)B + (size_t)(colBase + row) * (K * 2) + keB + kb);
        }
    };

    const int arow = wm * 64 + (lane & 15);
    const int akb = (lane >> 4) << 4;
    const int brow = wn * 64 + ((lane >> 4) << 3) + (lane & 7);
    const int bkb = (((lane >> 3) & 1)) << 4;

    auto lda = [&](uint32_t* af, uint32_t sb, int t) {
#pragma unroll
        for (int mi = 0; mi < 4; ++mi) {
            const int r = arow + mi * 16;
            ldsm4(af + mi * 4, sb + r * 128 + ((t * 32 + akb) ^ ((r & 7) << 4)));
        }
    };
    auto ldb = [&](uint32_t* bf, uint32_t sb, int t) {
#pragma unroll
        for (int bi = 0; bi < 4; ++bi) {
            const int r = brow + bi * 16;
            ldsm4(bf + bi * 4,
                  sb + APLANE + r * 128 + ((t * 32 + bkb) ^ ((r & 7) << 4)));
        }
    };

    float acc[4][8][4];
#pragma unroll
    for (int i = 0; i < 4; ++i)
#pragma unroll
        for (int j = 0; j < 8; ++j)
#pragma unroll
            for (int e = 0; e < 4; ++e) acc[i][j][e] = 0.f;

    load_stage(0, 0);
    CP_COMMIT();
    load_stage(1, 1);
    CP_COMMIT();
    CP_WAIT1();
    __syncthreads();

    uint32_t af[2][16], bf[2][16];
    lda(af[0], sb0, 0);
    ldb(bf[0], sb0, 0);

    for (int kc = 0; kc < NC; ++kc) {
        __syncthreads();
        if (kc + 2 < NC) {
            load_stage(kc + 2, (kc + 2) % 3);
            CP_COMMIT();
        }
        const uint32_t sb = sb0 + (kc % 3) * STAGE;
        const uint32_t sbn = sb0 + ((kc + 1) % 3) * STAGE;
#pragma unroll
        for (int t = 0; t < 4; ++t) {
            const int cur = t & 1, nxt = cur ^ 1;
            if (t < 3) {
                lda(af[nxt], sb, t + 1);
                ldb(bf[nxt], sb, t + 1);
            } else if (kc + 1 < NC) {
                if (kc + 2 < NC) { CP_WAIT1(); } else { CP_WAIT0(); }
                lda(af[nxt], sbn, 0);
                ldb(bf[nxt], sbn, 0);
            }
#pragma unroll
            for (int mi = 0; mi < 4; ++mi)
#pragma unroll
                for (int ni = 0; ni < 8; ++ni)
                    mma_f16(acc[mi][ni], &af[cur][mi * 4], &bf[cur][ni * 2]);
        }
    }

#pragma unroll
    for (int mi = 0; mi < 4; ++mi) {
#pragma unroll
        for (int ni = 0; ni < 8; ++ni) {
            const int col = colBase + wn * 64 + ni * 8 + tig * 2;
#pragma unroll
            for (int hf = 0; hf < 2; ++hf) {
                const int row = rowBase + wm * 64 + mi * 16 + gid + hf * 8;
                if (EPI == 0) {
                    const float2 bb = *reinterpret_cast<const float2*>(bias + col);
                    const float v0 = tanh_fast(acc[mi][ni][hf * 2 + 0] + bb.x);
                    const float v1 = tanh_fast(acc[mi][ni][hf * 2 + 1] + bb.y);
                    *reinterpret_cast<__half2*>(H + (size_t)row * HID + col) =
                        __floats2half2_rn(v0, v1);
                } else {
                    *reinterpret_cast<__half2*>(P + (size_t)row * DIM + col) =
                        __floats2half2_rn(acc[mi][ni][hf * 2 + 0],
                                          acc[mi][ni][hf * 2 + 1]);
                }
            }
        }
    }
}

// GEMM1: H = tanh(Y @ W1^T + b1); grid (32, 8)
__global__ void __launch_bounds__(128, 2)
hgemm1(const __half* __restrict__ A, const __half* __restrict__ B,
       const float* __restrict__ bias, __half* __restrict__ H) {
    extern __shared__ char smem[];
    gemm_body<0>(A, B, bias, H, nullptr, 1024, 0, 16, smem);
}

// GEMM2 (split-K x4): P[z] = H @ W2^T slice (fp16 partials); grid (8, 8, 4)
__global__ void __launch_bounds__(128, 2)
hgemm2(const __half* __restrict__ A, const __half* __restrict__ B,
       __half* __restrict__ P) {
    extern __shared__ char smem[];
    gemm_body<1>(A, B, nullptr, nullptr, P + (size_t)blockIdx.z * BD, 4096,
                 (size_t)blockIdx.z * 2048, 16, smem);
}

// -------- reduce + RK4 stage update (fp32 master state chain) --------
template <int EPI>
__global__ void kreduce(const __half* __restrict__ P, const float* __restrict__ b2,
                        const float* __restrict__ ybase, float* __restrict__ Yacc,
                        float* __restrict__ yout, __half* __restrict__ Yh,
                        const float* __restrict__ tspan, int step) {
    const int idx = blockIdx.x * 256 + threadIdx.x;
    const size_t i4 = (size_t)idx * 4;
    const float h = tspan[step + 1] - tspan[step];

    float4 k;
    {
        const float4 bb = *reinterpret_cast<const float4*>(b2 + (i4 & 1023));
        k = bb;
#pragma unroll
        for (int z = 0; z < 4; ++z) {
            const uint2 pr =
                *reinterpret_cast<const uint2*>(P + (size_t)z * BD + i4);
            __half2 p01, p23;
            memcpy(&p01, &pr.x, 4);
            memcpy(&p23, &pr.y, 4);
            const float2 f01 = __half22float2(p01);
            const float2 f23 = __half22float2(p23);
            k.x += f01.x;
            k.y += f01.y;
            k.z += f23.x;
            k.w += f23.y;
        }
    }

    float4 o;
    if (EPI == 4) {
        const float4 aa = *reinterpret_cast<const float4*>(Yacc + i4);
        o.x = fmaf(h * (1.f / 6.f), k.x, aa.x);
        o.y = fmaf(h * (1.f / 6.f), k.y, aa.y);
        o.z = fmaf(h * (1.f / 6.f), k.z, aa.z);
        o.w = fmaf(h * (1.f / 6.f), k.w, aa.w);
        *reinterpret_cast<float4*>(yout + i4) = o;
    } else {
        const float4 yy = *reinterpret_cast<const float4*>(ybase + i4);
        const float cy = (EPI == 3) ? 1.0f : 0.5f;
        o.x = fmaf(cy * h, k.x, yy.x);
        o.y = fmaf(cy * h, k.y, yy.y);
        o.z = fmaf(cy * h, k.z, yy.z);
        o.w = fmaf(cy * h, k.w, yy.w);
        float4 aa;
        if (EPI == 1) {
            aa.x = fmaf(h * (1.f / 6.f), k.x, yy.x);
            aa.y = fmaf(h * (1.f / 6.f), k.y, yy.y);
            aa.z = fmaf(h * (1.f / 6.f), k.z, yy.z);
            aa.w = fmaf(h * (1.f / 6.f), k.w, yy.w);
        } else {
            aa = *reinterpret_cast<const float4*>(Yacc + i4);
            aa.x = fmaf(h * (1.f / 3.f), k.x, aa.x);
            aa.y = fmaf(h * (1.f / 3.f), k.y, aa.y);
            aa.z = fmaf(h * (1.f / 3.f), k.z, aa.z);
            aa.w = fmaf(h * (1.f / 3.f), k.w, aa.w);
        }
        *reinterpret_cast<float4*>(Yacc + i4) = aa;
    }
    __half2 h01 = __floats2half2_rn(o.x, o.y);
    __half2 h23 = __floats2half2_rn(o.z, o.w);
    uint2 hp;
    memcpy(&hp.x, &h01, 4);
    memcpy(&hp.y, &h23, 4);
    *reinterpret_cast<uint2*>(Yh + i4) = hp;
}

// fp32 [R,C] -> fp16 plane [C,R] (transpose + round)
__global__ void ktrans_h(const float* __restrict__ in, __half* __restrict__ oh,
                         int R, int C) {
    __shared__ float t[32][33];
    const int bx = blockIdx.x * 32;
    const int by = blockIdx.y * 32;
    for (int i = threadIdx.y; i < 32; i += 8)
        t[i][threadIdx.x] = in[(size_t)(by + i) * C + bx + threadIdx.x];
    __syncthreads();
    for (int i = threadIdx.y; i < 32; i += 8)
        oh[(size_t)(bx + i) * R + by + threadIdx.x] = __float2half(t[threadIdx.x][i]);
}

__global__ void ky(const float* __restrict__ in, __half* __restrict__ oh, int n) {
    int i = blockIdx.x * 256 + threadIdx.x;
    if (i < n) oh[i] = __float2half(in[i]);
}

extern "C" void kernel_launch(void* const* d_in, const int* in_sizes, int n_in,
                              void* d_out, int out_size) {
    const float* y_init = (const float*)d_in[0];
    const float* tspan = (const float*)d_in[1];
    const float* W1 = (const float*)d_in[2];
    const float* b1 = (const float*)d_in[3];
    const float* W2 = (const float*)d_in[4];
    const float* b2 = (const float*)d_in[5];
    float* out = (float*)d_out;

    __half *W1p, *W2p, *H, *Yh, *P;
    float* Yacc;
    cudaGetSymbolAddress((void**)&W1p, g_W1);
    cudaGetSymbolAddress((void**)&W2p, g_W2);
    cudaGetSymbolAddress((void**)&H, g_H);
    cudaGetSymbolAddress((void**)&Yh, g_Yh);
    cudaGetSymbolAddress((void**)&Yacc, g_Yacc);
    cudaGetSymbolAddress((void**)&P, g_P);

    const int SMEM = 3 * 2 * 128 * 128;  // 3 stages x 32 KB = 98304
    cudaFuncSetAttribute(hgemm1, cudaFuncAttributeMaxDynamicSharedMemorySize, SMEM);
    cudaFuncSetAttribute(hgemm2, cudaFuncAttributeMaxDynamicSharedMemorySize, SMEM);

    cudaMemcpyAsync(out, tspan, TSTEPS * sizeof(float), cudaMemcpyDeviceToDevice, 0);
    float* traj = out + TSTEPS;
    cudaMemcpyAsync(traj, y_init, (size_t)BD * sizeof(float), cudaMemcpyDeviceToDevice, 0);

    ktrans_h<<<dim3(HID / 32, DIM / 32), dim3(32, 8)>>>(W1, W1p, DIM, HID);
    ktrans_h<<<dim3(DIM / 32, HID / 32), dim3(32, 8)>>>(W2, W2p, HID, DIM);
    ky<<<BD / 256, 256>>>(y_init, Yh, BD);

    const dim3 g1(HID / 128, BATCH / 128);      // (32, 8) = 256 CTAs
    const dim3 g2(DIM / 128, BATCH / 128, 4);   // (8, 8, 4) = 256 CTAs

    for (int s = 0; s < TSTEPS - 1; ++s) {
        const float* y = traj + (size_t)s * BD;
        float* ynext = traj + (size_t)(s + 1) * BD;

        hgemm1<<<g1, 128, SMEM>>>(Yh, W1p, b1, H);
        hgemm2<<<g2, 128, SMEM>>>(H, W2p, P);
        kreduce<1><<<BD / 1024, 256>>>(P, b2, y, Yacc, nullptr, Yh, tspan, s);

        hgemm1<<<g1, 128, SMEM>>>(Yh, W1p, b1, H);
        hgemm2<<<g2, 128, SMEM>>>(H, W2p, P);
        kreduce<2><<<BD / 1024, 256>>>(P, b2, y, Yacc, nullptr, Yh, tspan, s);

        hgemm1<<<g1, 128, SMEM>>>(Yh, W1p, b1, H);
        hgemm2<<<g2, 128, SMEM>>>(H, W2p, P);
        kreduce<3><<<BD / 1024, 256>>>(P, b2, y, Yacc, nullptr, Yh, tspan, s);

        hgemm1<<<g1, 128, SMEM>>>(Yh, W1p, b1, H);
        hgemm2<<<g2, 128, SMEM>>>(H, W2p, P);
        kreduce<4><<<BD / 1024, 256>>>(P, b2, nullptr, Yacc, ynext, Yh, tspan, s);
    }
}

// round 16
// speedup vs baseline: 1.4492x; 1.0307x over previous
#include <cuda_runtime.h>
#include <cuda_fp16.h>
#include <cstdint>
#include <cstddef>
#include <cstring>

#define BATCH 1024
#define DIM   1024
#define HID   4096
#define TSTEPS 16
#define BD (BATCH*DIM)
#define HALF_ROWS 512

__device__ __half g_W1[(size_t)HID * DIM];   // W1^T fp16 [4096,1024]
__device__ __half g_W2[(size_t)DIM * HID];   // W2^T fp16 [1024,4096]
__device__ __half g_H[(size_t)BATCH * HID];  // hidden fp16
__device__ __half g_Yh[BD];                  // state fp16 (rounded)
__device__ float  g_Yacc[BD];                // RK4 accumulator (fp32)
__device__ __half g_P[(size_t)4 * BD];       // split-K partials (fp16)

__device__ __forceinline__ uint32_t smem_u32(const void* p) {
    uint32_t a;
    asm("{ .reg .u64 t; cvta.to.shared.u64 t, %1; cvt.u32.u64 %0, t; }" : "=r"(a) : "l"(p));
    return a;
}
__device__ __forceinline__ void cpa16(uint32_t s, const void* g) {
    asm volatile("cp.async.cg.shared.global [%0], [%1], 16;"
                 :: "r"(s), "l"(__cvta_generic_to_global(g)));
}
#define CP_COMMIT() asm volatile("cp.async.commit_group;" ::: "memory")
#define CP_WAIT0()  asm volatile("cp.async.wait_group 0;" ::: "memory")
#define CP_WAIT1()  asm volatile("cp.async.wait_group 1;" ::: "memory")

__device__ __forceinline__ void ldsm4(uint32_t* r, uint32_t addr) {
    asm volatile("ldmatrix.sync.aligned.m8n8.x4.shared.b16 {%0,%1,%2,%3}, [%4];"
                 : "=r"(r[0]), "=r"(r[1]), "=r"(r[2]), "=r"(r[3]) : "r"(addr));
}
__device__ __forceinline__ void mma_f16(float* d, const uint32_t* a, const uint32_t* b) {
    asm volatile(
        "mma.sync.aligned.m16n8k16.row.col.f32.f16.f16.f32 "
        "{%0,%1,%2,%3}, {%4,%5,%6,%7}, {%8,%9}, {%0,%1,%2,%3};"
        : "+f"(d[0]), "+f"(d[1]), "+f"(d[2]), "+f"(d[3])
        : "r"(a[0]), "r"(a[1]), "r"(a[2]), "r"(a[3]), "r"(b[0]), "r"(b[1]));
}
__device__ __forceinline__ float tanh_fast(float x) {
    asm("tanh.approx.f32 %0, %0;" : "+f"(x));
    return x;
}

// Shared GEMM body (R13/R15): C tile [128 x 128] of A[M,K] @ B[N,K]^T.
// 128 threads = 4 warps (2M x 2N), warp tile 64x64. 2 CTAs/SM. 3-stage ring,
// next-chunk t0 fragments preloaded mid-chunk. rowOff selects the batch half.
// EPI=0: H = tanh(acc + bias) fp16 out.  EPI=1: P = acc fp16 out (split-K).
template <int EPI>
__device__ __forceinline__ void gemm_body(
    const __half* A, const __half* B, const float* bias, __half* H,
    __half* P, int K, size_t kzB, int NC, int rowOff, char* smem) {
    constexpr int APLANE = 128 * 128;   // 16 KB
    constexpr int STAGE = 2 * APLANE;   // 32 KB
    const uint32_t sb0 = smem_u32(smem);

    const int tid = threadIdx.x;
    const int wid = tid >> 5, lane = tid & 31;
    const int wm = wid & 1, wn = wid >> 1;
    const int gid = lane >> 2, tig = lane & 3;
    const int rowBase = rowOff + blockIdx.y * 128;
    const int colBase = blockIdx.x * 128;

    auto load_stage = [&](int kc, int st) {
        const uint32_t sb = sb0 + st * STAGE;
        const size_t keB = kzB + (size_t)kc * 128;
#pragma unroll
        for (int c = tid; c < 128 * 8; c += 128) {
            const int row = c >> 3, kb = (c & 7) << 4;
            const uint32_t so = row * 128 + (kb ^ ((row & 7) << 4));
            cpa16(sb + so, (const char*)A + (size_t)(rowBase + row) * (K * 2) + keB + kb);
            cpa16(sb + APLANE + so,
                  (const char*)B + (size_t)(colBase + row) * (K * 2) + keB + kb);
        }
    };

    const int arow = wm * 64 + (lane & 15);
    const int akb = (lane >> 4) << 4;
    const int brow = wn * 64 + ((lane >> 4) << 3) + (lane & 7);
    const int bkb = (((lane >> 3) & 1)) << 4;

    auto lda = [&](uint32_t* af, uint32_t sb, int t) {
#pragma unroll
        for (int mi = 0; mi < 4; ++mi) {
            const int r = arow + mi * 16;
            ldsm4(af + mi * 4, sb + r * 128 + ((t * 32 + akb) ^ ((r & 7) << 4)));
        }
    };
    auto ldb = [&](uint32_t* bf, uint32_t sb, int t) {
#pragma unroll
        for (int bi = 0; bi < 4; ++bi) {
            const int r = brow + bi * 16;
            ldsm4(bf + bi * 4,
                  sb + APLANE + r * 128 + ((t * 32 + bkb) ^ ((r & 7) << 4)));
        }
    };

    float acc[4][8][4];
#pragma unroll
    for (int i = 0; i < 4; ++i)
#pragma unroll
        for (int j = 0; j < 8; ++j)
#pragma unroll
            for (int e = 0; e < 4; ++e) acc[i][j][e] = 0.f;

    load_stage(0, 0);
    CP_COMMIT();
    load_stage(1, 1);
    CP_COMMIT();
    CP_WAIT1();
    __syncthreads();

    uint32_t af[2][16], bf[2][16];
    lda(af[0], sb0, 0);
    ldb(bf[0], sb0, 0);

    for (int kc = 0; kc < NC; ++kc) {
        __syncthreads();
        if (kc + 2 < NC) {
            load_stage(kc + 2, (kc + 2) % 3);
            CP_COMMIT();
        }
        const uint32_t sb = sb0 + (kc % 3) * STAGE;
        const uint32_t sbn = sb0 + ((kc + 1) % 3) * STAGE;
#pragma unroll
        for (int t = 0; t < 4; ++t) {
            const int cur = t & 1, nxt = cur ^ 1;
            if (t < 3) {
                lda(af[nxt], sb, t + 1);
                ldb(bf[nxt], sb, t + 1);
            } else if (kc + 1 < NC) {
                if (kc + 2 < NC) { CP_WAIT1(); } else { CP_WAIT0(); }
                lda(af[nxt], sbn, 0);
                ldb(bf[nxt], sbn, 0);
            }
#pragma unroll
            for (int mi = 0; mi < 4; ++mi)
#pragma unroll
                for (int ni = 0; ni < 8; ++ni)
                    mma_f16(acc[mi][ni], &af[cur][mi * 4], &bf[cur][ni * 2]);
        }
    }

#pragma unroll
    for (int mi = 0; mi < 4; ++mi) {
#pragma unroll
        for (int ni = 0; ni < 8; ++ni) {
            const int col = colBase + wn * 64 + ni * 8 + tig * 2;
#pragma unroll
            for (int hf = 0; hf < 2; ++hf) {
                const int row = rowBase + wm * 64 + mi * 16 + gid + hf * 8;
                if (EPI == 0) {
                    const float2 bb = *reinterpret_cast<const float2*>(bias + col);
                    const float v0 = tanh_fast(acc[mi][ni][hf * 2 + 0] + bb.x);
                    const float v1 = tanh_fast(acc[mi][ni][hf * 2 + 1] + bb.y);
                    *reinterpret_cast<__half2*>(H + (size_t)row * HID + col) =
                        __floats2half2_rn(v0, v1);
                } else {
                    *reinterpret_cast<__half2*>(P + (size_t)row * DIM + col) =
                        __floats2half2_rn(acc[mi][ni][hf * 2 + 0],
                                          acc[mi][ni][hf * 2 + 1]);
                }
            }
        }
    }
}

// GEMM1 half: H = tanh(Y @ W1^T + b1); grid (32, 4)
__global__ void __launch_bounds__(128, 2)
hgemm1(const __half* __restrict__ A, const __half* __restrict__ B,
       const float* __restrict__ bias, __half* __restrict__ H, int rowOff) {
    extern __shared__ char smem[];
    gemm_body<0>(A, B, bias, H, nullptr, 1024, 0, 16, rowOff, smem);
}

// GEMM2 half (split-K x4): P[z] = H @ W2^T slice; grid (8, 4, 4)
__global__ void __launch_bounds__(128, 2)
hgemm2(const __half* __restrict__ A, const __half* __restrict__ B,
       __half* __restrict__ P, int rowOff) {
    extern __shared__ char smem[];
    gemm_body<1>(A, B, nullptr, nullptr, P + (size_t)blockIdx.z * BD, 4096,
                 (size_t)blockIdx.z * 2048, 16, rowOff, smem);
}

// -------- reduce + RK4 stage update (fp32 master state chain), half --------
template <int EPI>
__global__ void kreduce(const __half* __restrict__ P, const float* __restrict__ b2,
                        const float* __restrict__ ybase, float* __restrict__ Yacc,
                        float* __restrict__ yout, __half* __restrict__ Yh,
                        const float* __restrict__ tspan, int step, int rowOff) {
    const int idx = blockIdx.x * 256 + threadIdx.x;
    const size_t i4 = (size_t)rowOff * DIM + (size_t)idx * 4;
    const float h = tspan[step + 1] - tspan[step];

    float4 k;
    {
        const float4 bb = *reinterpret_cast<const float4*>(b2 + (i4 & 1023));
        k = bb;
#pragma unroll
        for (int z = 0; z < 4; ++z) {
            const uint2 pr =
                *reinterpret_cast<const uint2*>(P + (size_t)z * BD + i4);
            __half2 p01, p23;
            memcpy(&p01, &pr.x, 4);
            memcpy(&p23, &pr.y, 4);
            const float2 f01 = __half22float2(p01);
            const float2 f23 = __half22float2(p23);
            k.x += f01.x;
            k.y += f01.y;
            k.z += f23.x;
            k.w += f23.y;
        }
    }

    float4 o;
    if (EPI == 4) {
        const float4 aa = *reinterpret_cast<const float4*>(Yacc + i4);
        o.x = fmaf(h * (1.f / 6.f), k.x, aa.x);
        o.y = fmaf(h * (1.f / 6.f), k.y, aa.y);
        o.z = fmaf(h * (1.f / 6.f), k.z, aa.z);
        o.w = fmaf(h * (1.f / 6.f), k.w, aa.w);
        *reinterpret_cast<float4*>(yout + i4) = o;
    } else {
        const float4 yy = *reinterpret_cast<const float4*>(ybase + i4);
        const float cy = (EPI == 3) ? 1.0f : 0.5f;
        o.x = fmaf(cy * h, k.x, yy.x);
        o.y = fmaf(cy * h, k.y, yy.y);
        o.z = fmaf(cy * h, k.z, yy.z);
        o.w = fmaf(cy * h, k.w, yy.w);
        float4 aa;
        if (EPI == 1) {
            aa.x = fmaf(h * (1.f / 6.f), k.x, yy.x);
            aa.y = fmaf(h * (1.f / 6.f), k.y, yy.y);
            aa.z = fmaf(h * (1.f / 6.f), k.z, yy.z);
            aa.w = fmaf(h * (1.f / 6.f), k.w, yy.w);
        } else {
            aa = *reinterpret_cast<const float4*>(Yacc + i4);
            aa.x = fmaf(h * (1.f / 3.f), k.x, aa.x);
            aa.y = fmaf(h * (1.f / 3.f), k.y, aa.y);
            aa.z = fmaf(h * (1.f / 3.f), k.z, aa.z);
            aa.w = fmaf(h * (1.f / 3.f), k.w, aa.w);
        }
        *reinterpret_cast<float4*>(Yacc + i4) = aa;
    }
    __half2 h01 = __floats2half2_rn(o.x, o.y);
    __half2 h23 = __floats2half2_rn(o.z, o.w);
    uint2 hp;
    memcpy(&hp.x, &h01, 4);
    memcpy(&hp.y, &h23, 4);
    *reinterpret_cast<uint2*>(Yh + i4) = hp;
}

// fp32 [R,C] -> fp16 plane [C,R] (transpose + round)
__global__ void ktrans_h(const float* __restrict__ in, __half* __restrict__ oh,
                         int R, int C) {
    __shared__ float t[32][33];
    const int bx = blockIdx.x * 32;
    const int by = blockIdx.y * 32;
    for (int i = threadIdx.y; i < 32; i += 8)
        t[i][threadIdx.x] = in[(size_t)(by + i) * C + bx + threadIdx.x];
    __syncthreads();
    for (int i = threadIdx.y; i < 32; i += 8)
        oh[(size_t)(bx + i) * R + by + threadIdx.x] = __float2half(t[threadIdx.x][i]);
}

__global__ void ky(const float* __restrict__ in, __half* __restrict__ oh, int n) {
    int i = blockIdx.x * 256 + threadIdx.x;
    if (i < n) oh[i] = __float2half(in[i]);
}

extern "C" void kernel_launch(void* const* d_in, const int* in_sizes, int n_in,
                              void* d_out, int out_size) {
    const float* y_init = (const float*)d_in[0];
    const float* tspan = (const float*)d_in[1];
    const float* W1 = (const float*)d_in[2];
    const float* b1 = (const float*)d_in[3];
    const float* W2 = (const float*)d_in[4];
    const float* b2 = (const float*)d_in[5];
    float* out = (float*)d_out;

    __half *W1p, *W2p, *H, *Yh, *P;
    float* Yacc;
    cudaGetSymbolAddress((void**)&W1p, g_W1);
    cudaGetSymbolAddress((void**)&W2p, g_W2);
    cudaGetSymbolAddress((void**)&H, g_H);
    cudaGetSymbolAddress((void**)&Yh, g_Yh);
    cudaGetSymbolAddress((void**)&Yacc, g_Yacc);
    cudaGetSymbolAddress((void**)&P, g_P);

    // one-time infra (host objects only; created on first, uncaptured call)
    static cudaStream_t s2 = nullptr;
    static cudaEvent_t evFork = nullptr, evJoin = nullptr;
    if (!s2) {
        cudaStreamCreateWithFlags(&s2, cudaStreamNonBlocking);
        cudaEventCreateWithFlags(&evFork, cudaEventDisableTiming);
        cudaEventCreateWithFlags(&evJoin, cudaEventDisableTiming);
    }

    const int SMEM = 3 * 2 * 128 * 128;  // 98304
    cudaFuncSetAttribute(hgemm1, cudaFuncAttributeMaxDynamicSharedMemorySize, SMEM);
    cudaFuncSetAttribute(hgemm2, cudaFuncAttributeMaxDynamicSharedMemorySize, SMEM);

    cudaMemcpyAsync(out, tspan, TSTEPS * sizeof(float), cudaMemcpyDeviceToDevice, 0);
    float* traj = out + TSTEPS;
    cudaMemcpyAsync(traj, y_init, (size_t)BD * sizeof(float), cudaMemcpyDeviceToDevice, 0);

    ktrans_h<<<dim3(HID / 32, DIM / 32), dim3(32, 8)>>>(W1, W1p, DIM, HID);
    ktrans_h<<<dim3(DIM / 32, HID / 32), dim3(32, 8)>>>(W2, W2p, HID, DIM);
    ky<<<BD / 256, 256>>>(y_init, Yh, BD);

    // fork: half A (rows 0-511) on default stream, half B (512-1023) on s2
    cudaEventRecord(evFork, 0);
    cudaStreamWaitEvent(s2, evFork, 0);

    const dim3 g1(HID / 128, HALF_ROWS / 128);      // (32, 4) = 128 CTAs
    const dim3 g2(DIM / 128, HALF_ROWS / 128, 4);   // (8, 4, 4) = 128 CTAs
    const int RB = (HALF_ROWS * DIM) / 1024;        // 512 reduce blocks

    for (int s = 0; s < TSTEPS - 1; ++s) {
        const float* y = traj + (size_t)s * BD;
        float* ynext = traj + (size_t)(s + 1) * BD;

#define STAGE_HALF(EPIv, strm, roff, yb, yo)                                   \
        hgemm1<<<g1, 128, SMEM, strm>>>(Yh, W1p, b1, H, roff);                 \
        hgemm2<<<g2, 128, SMEM, strm>>>(H, W2p, P, roff);                      \
        kreduce<EPIv><<<RB, 256, 0, strm>>>(P, b2, yb, Yacc, yo, Yh, tspan, s, roff)

        STAGE_HALF(1, 0, 0, y, nullptr);
        STAGE_HALF(1, s2, HALF_ROWS, y, nullptr);
        STAGE_HALF(2, 0, 0, y, nullptr);
        STAGE_HALF(2, s2, HALF_ROWS, y, nullptr);
        STAGE_HALF(3, 0, 0, y, nullptr);
        STAGE_HALF(3, s2, HALF_ROWS, y, nullptr);
        STAGE_HALF(4, 0, 0, nullptr, ynext);
        STAGE_HALF(4, s2, HALF_ROWS, nullptr, ynext);
#undef STAGE_HALF
    }

    // join
    cudaEventRecord(evJoin, s2);
    cudaStreamWaitEvent(0, evJoin, 0);
}

// round 17
// speedup vs baseline: 1.4686x; 1.0134x over previous
#include <cuda_runtime.h>
#include <cuda_fp16.h>
#include <cstdint>
#include <cstddef>
#include <cstring>

#define BATCH 1024
#define DIM   1024
#define HID   4096
#define TSTEPS 16
#define BD (BATCH*DIM)
#define QROWS 256

__device__ __half g_W1[(size_t)HID * DIM];   // W1^T fp16 [4096,1024]
__device__ __half g_W2[(size_t)DIM * HID];   // W2^T fp16 [1024,4096]
__device__ __half g_H[(size_t)BATCH * HID];  // hidden fp16
__device__ __half g_Yh[BD];                  // state fp16 (rounded)
__device__ float  g_Yacc[BD];                // RK4 accumulator (fp32)
__device__ __half g_P[(size_t)4 * BD];       // split-K partials (fp16)

__device__ __forceinline__ uint32_t smem_u32(const void* p) {
    uint32_t a;
    asm("{ .reg .u64 t; cvta.to.shared.u64 t, %1; cvt.u32.u64 %0, t; }" : "=r"(a) : "l"(p));
    return a;
}
__device__ __forceinline__ void cpa16(uint32_t s, const void* g) {
    asm volatile("cp.async.cg.shared.global [%0], [%1], 16;"
                 :: "r"(s), "l"(__cvta_generic_to_global(g)));
}
#define CP_COMMIT() asm volatile("cp.async.commit_group;" ::: "memory")
#define CP_WAIT0()  asm volatile("cp.async.wait_group 0;" ::: "memory")
#define CP_WAIT1()  asm volatile("cp.async.wait_group 1;" ::: "memory")

__device__ __forceinline__ void ldsm4(uint32_t* r, uint32_t addr) {
    asm volatile("ldmatrix.sync.aligned.m8n8.x4.shared.b16 {%0,%1,%2,%3}, [%4];"
                 : "=r"(r[0]), "=r"(r[1]), "=r"(r[2]), "=r"(r[3]) : "r"(addr));
}
__device__ __forceinline__ void mma_f16(float* d, const uint32_t* a, const uint32_t* b) {
    asm volatile(
        "mma.sync.aligned.m16n8k16.row.col.f32.f16.f16.f32 "
        "{%0,%1,%2,%3}, {%4,%5,%6,%7}, {%8,%9}, {%0,%1,%2,%3};"
        : "+f"(d[0]), "+f"(d[1]), "+f"(d[2]), "+f"(d[3])
        : "r"(a[0]), "r"(a[1]), "r"(a[2]), "r"(a[3]), "r"(b[0]), "r"(b[1]));
}
__device__ __forceinline__ float tanh_fast(float x) {
    asm("tanh.approx.f32 %0, %0;" : "+f"(x));
    return x;
}

// Shared GEMM body (R13): C tile [128 x 128] of A[M,K] @ B[N,K]^T.
// 128 threads = 4 warps (2M x 2N), warp tile 64x64. 2 CTAs/SM. 3-stage ring,
// next-chunk t0 fragments preloaded mid-chunk. rowOff selects the batch slice.
// EPI=0: H = tanh(acc + bias) fp16 out.  EPI=1: P = acc fp16 out (split-K).
template <int EPI>
__device__ __forceinline__ void gemm_body(
    const __half* A, const __half* B, const float* bias, __half* H,
    __half* P, int K, size_t kzB, int NC, int rowOff, char* smem) {
    constexpr int APLANE = 128 * 128;   // 16 KB
    constexpr int STAGE = 2 * APLANE;   // 32 KB
    const uint32_t sb0 = smem_u32(smem);

    const int tid = threadIdx.x;
    const int wid = tid >> 5, lane = tid & 31;
    const int wm = wid & 1, wn = wid >> 1;
    const int gid = lane >> 2, tig = lane & 3;
    const int rowBase = rowOff + blockIdx.y * 128;
    const int colBase = blockIdx.x * 128;

    auto load_stage = [&](int kc, int st) {
        const uint32_t sb = sb0 + st * STAGE;
        const size_t keB = kzB + (size_t)kc * 128;
#pragma unroll
        for (int c = tid; c < 128 * 8; c += 128) {
            const int row = c >> 3, kb = (c & 7) << 4;
            const uint32_t so = row * 128 + (kb ^ ((row & 7) << 4));
            cpa16(sb + so, (const char*)A + (size_t)(rowBase + row) * (K * 2) + keB + kb);
            cpa16(sb + APLANE + so,
                  (const char*)B + (size_t)(colBase + row) * (K * 2) + keB + kb);
        }
    };

    const int arow = wm * 64 + (lane & 15);
    const int akb = (lane >> 4) << 4;
    const int brow = wn * 64 + ((lane >> 4) << 3) + (lane & 7);
    const int bkb = (((lane >> 3) & 1)) << 4;

    auto lda = [&](uint32_t* af, uint32_t sb, int t) {
#pragma unroll
        for (int mi = 0; mi < 4; ++mi) {
            const int r = arow + mi * 16;
            ldsm4(af + mi * 4, sb + r * 128 + ((t * 32 + akb) ^ ((r & 7) << 4)));
        }
    };
    auto ldb = [&](uint32_t* bf, uint32_t sb, int t) {
#pragma unroll
        for (int bi = 0; bi < 4; ++bi) {
            const int r = brow + bi * 16;
            ldsm4(bf + bi * 4,
                  sb + APLANE + r * 128 + ((t * 32 + bkb) ^ ((r & 7) << 4)));
        }
    };

    float acc[4][8][4];
#pragma unroll
    for (int i = 0; i < 4; ++i)
#pragma unroll
        for (int j = 0; j < 8; ++j)
#pragma unroll
            for (int e = 0; e < 4; ++e) acc[i][j][e] = 0.f;

    load_stage(0, 0);
    CP_COMMIT();
    load_stage(1, 1);
    CP_COMMIT();
    CP_WAIT1();
    __syncthreads();

    uint32_t af[2][16], bf[2][16];
    lda(af[0], sb0, 0);
    ldb(bf[0], sb0, 0);

    for (int kc = 0; kc < NC; ++kc) {
        __syncthreads();
        if (kc + 2 < NC) {
            load_stage(kc + 2, (kc + 2) % 3);
            CP_COMMIT();
        }
        const uint32_t sb = sb0 + (kc % 3) * STAGE;
        const uint32_t sbn = sb0 + ((kc + 1) % 3) * STAGE;
#pragma unroll
        for (int t = 0; t < 4; ++t) {
            const int cur = t & 1, nxt = cur ^ 1;
            if (t < 3) {
                lda(af[nxt], sb, t + 1);
                ldb(bf[nxt], sb, t + 1);
            } else if (kc + 1 < NC) {
                if (kc + 2 < NC) { CP_WAIT1(); } else { CP_WAIT0(); }
                lda(af[nxt], sbn, 0);
                ldb(bf[nxt], sbn, 0);
            }
#pragma unroll
            for (int mi = 0; mi < 4; ++mi)
#pragma unroll
                for (int ni = 0; ni < 8; ++ni)
                    mma_f16(acc[mi][ni], &af[cur][mi * 4], &bf[cur][ni * 2]);
        }
    }

#pragma unroll
    for (int mi = 0; mi < 4; ++mi) {
#pragma unroll
        for (int ni = 0; ni < 8; ++ni) {
            const int col = colBase + wn * 64 + ni * 8 + tig * 2;
#pragma unroll
            for (int hf = 0; hf < 2; ++hf) {
                const int row = rowBase + wm * 64 + mi * 16 + gid + hf * 8;
                if (EPI == 0) {
                    const float2 bb = *reinterpret_cast<const float2*>(bias + col);
                    const float v0 = tanh_fast(acc[mi][ni][hf * 2 + 0] + bb.x);
                    const float v1 = tanh_fast(acc[mi][ni][hf * 2 + 1] + bb.y);
                    *reinterpret_cast<__half2*>(H + (size_t)row * HID + col) =
                        __floats2half2_rn(v0, v1);
                } else {
                    *reinterpret_cast<__half2*>(P + (size_t)row * DIM + col) =
                        __floats2half2_rn(acc[mi][ni][hf * 2 + 0],
                                          acc[mi][ni][hf * 2 + 1]);
                }
            }
        }
    }
}

// GEMM1 quarter: H = tanh(Y @ W1^T + b1); grid (32, 2) = 64 CTAs
__global__ void __launch_bounds__(128, 2)
hgemm1(const __half* __restrict__ A, const __half* __restrict__ B,
       const float* __restrict__ bias, __half* __restrict__ H, int rowOff) {
    extern __shared__ char smem[];
    gemm_body<0>(A, B, bias, H, nullptr, 1024, 0, 16, rowOff, smem);
}

// GEMM2 quarter (split-K x4): P[z] = H @ W2^T slice; grid (8, 2, 4) = 64 CTAs
__global__ void __launch_bounds__(128, 2)
hgemm2(const __half* __restrict__ A, const __half* __restrict__ B,
       __half* __restrict__ P, int rowOff) {
    extern __shared__ char smem[];
    gemm_body<1>(A, B, nullptr, nullptr, P + (size_t)blockIdx.z * BD, 4096,
                 (size_t)blockIdx.z * 2048, 16, rowOff, smem);
}

// -------- reduce + RK4 stage update (fp32 master state chain), quarter --------
template <int EPI>
__global__ void kreduce(const __half* __restrict__ P, const float* __restrict__ b2,
                        const float* __restrict__ ybase, float* __restrict__ Yacc,
                        float* __restrict__ yout, __half* __restrict__ Yh,
                        const float* __restrict__ tspan, int step, int rowOff) {
    const int idx = blockIdx.x * 256 + threadIdx.x;
    const size_t i4 = (size_t)rowOff * DIM + (size_t)idx * 4;
    const float h = tspan[step + 1] - tspan[step];

    float4 k;
    {
        const float4 bb = *reinterpret_cast<const float4*>(b2 + (i4 & 1023));
        k = bb;
#pragma unroll
        for (int z = 0; z < 4; ++z) {
            const uint2 pr =
                *reinterpret_cast<const uint2*>(P + (size_t)z * BD + i4);
            __half2 p01, p23;
            memcpy(&p01, &pr.x, 4);
            memcpy(&p23, &pr.y, 4);
            const float2 f01 = __half22float2(p01);
            const float2 f23 = __half22float2(p23);
            k.x += f01.x;
            k.y += f01.y;
            k.z += f23.x;
            k.w += f23.y;
        }
    }

    float4 o;
    if (EPI == 4) {
        const float4 aa = *reinterpret_cast<const float4*>(Yacc + i4);
        o.x = fmaf(h * (1.f / 6.f), k.x, aa.x);
        o.y = fmaf(h * (1.f / 6.f), k.y, aa.y);
        o.z = fmaf(h * (1.f / 6.f), k.z, aa.z);
        o.w = fmaf(h * (1.f / 6.f), k.w, aa.w);
        *reinterpret_cast<float4*>(yout + i4) = o;
    } else {
        const float4 yy = *reinterpret_cast<const float4*>(ybase + i4);
        const float cy = (EPI == 3) ? 1.0f : 0.5f;
        o.x = fmaf(cy * h, k.x, yy.x);
        o.y = fmaf(cy * h, k.y, yy.y);
        o.z = fmaf(cy * h, k.z, yy.z);
        o.w = fmaf(cy * h, k.w, yy.w);
        float4 aa;
        if (EPI == 1) {
            aa.x = fmaf(h * (1.f / 6.f), k.x, yy.x);
            aa.y = fmaf(h * (1.f / 6.f), k.y, yy.y);
            aa.z = fmaf(h * (1.f / 6.f), k.z, yy.z);
            aa.w = fmaf(h * (1.f / 6.f), k.w, yy.w);
        } else {
            aa = *reinterpret_cast<const float4*>(Yacc + i4);
            aa.x = fmaf(h * (1.f / 3.f), k.x, aa.x);
            aa.y = fmaf(h * (1.f / 3.f), k.y, aa.y);
            aa.z = fmaf(h * (1.f / 3.f), k.z, aa.z);
            aa.w = fmaf(h * (1.f / 3.f), k.w, aa.w);
        }
        *reinterpret_cast<float4*>(Yacc + i4) = aa;
    }
    __half2 h01 = __floats2half2_rn(o.x, o.y);
    __half2 h23 = __floats2half2_rn(o.z, o.w);
    uint2 hp;
    memcpy(&hp.x, &h01, 4);
    memcpy(&hp.y, &h23, 4);
    *reinterpret_cast<uint2*>(Yh + i4) = hp;
}

// fp32 [R,C] -> fp16 plane [C,R] (transpose + round)
__global__ void ktrans_h(const float* __restrict__ in, __half* __restrict__ oh,
                         int R, int C) {
    __shared__ float t[32][33];
    const int bx = blockIdx.x * 32;
    const int by = blockIdx.y * 32;
    for (int i = threadIdx.y; i < 32; i += 8)
        t[i][threadIdx.x] = in[(size_t)(by + i) * C + bx + threadIdx.x];
    __syncthreads();
    for (int i = threadIdx.y; i < 32; i += 8)
        oh[(size_t)(bx + i) * R + by + threadIdx.x] = __float2half(t[threadIdx.x][i]);
}

__global__ void ky(const float* __restrict__ in, __half* __restrict__ oh, int n) {
    int i = blockIdx.x * 256 + threadIdx.x;
    if (i < n) oh[i] = __float2half(in[i]);
}

extern "C" void kernel_launch(void* const* d_in, const int* in_sizes, int n_in,
                              void* d_out, int out_size) {
    const float* y_init = (const float*)d_in[0];
    const float* tspan = (const float*)d_in[1];
    const float* W1 = (const float*)d_in[2];
    const float* b1 = (const float*)d_in[3];
    const float* W2 = (const float*)d_in[4];
    const float* b2 = (const float*)d_in[5];
    float* out = (float*)d_out;

    __half *W1p, *W2p, *H, *Yh, *P;
    float* Yacc;
    cudaGetSymbolAddress((void**)&W1p, g_W1);
    cudaGetSymbolAddress((void**)&W2p, g_W2);
    cudaGetSymbolAddress((void**)&H, g_H);
    cudaGetSymbolAddress((void**)&Yh, g_Yh);
    cudaGetSymbolAddress((void**)&Yacc, g_Yacc);
    cudaGetSymbolAddress((void**)&P, g_P);

    // one-time infra (host objects only; created on first, uncaptured call)
    static cudaStream_t sx[3] = {nullptr, nullptr, nullptr};
    static cudaEvent_t evFork = nullptr, evJoin[3] = {nullptr, nullptr, nullptr};
    if (!sx[0]) {
        for (int i = 0; i < 3; ++i) {
            cudaStreamCreateWithFlags(&sx[i], cudaStreamNonBlocking);
            cudaEventCreateWithFlags(&evJoin[i], cudaEventDisableTiming);
        }
        cudaEventCreateWithFlags(&evFork, cudaEventDisableTiming);
    }

    const int SMEM = 3 * 2 * 128 * 128;  // 98304
    cudaFuncSetAttribute(hgemm1, cudaFuncAttributeMaxDynamicSharedMemorySize, SMEM);
    cudaFuncSetAttribute(hgemm2, cudaFuncAttributeMaxDynamicSharedMemorySize, SMEM);

    cudaMemcpyAsync(out, tspan, TSTEPS * sizeof(float), cudaMemcpyDeviceToDevice, 0);
    float* traj = out + TSTEPS;
    cudaMemcpyAsync(traj, y_init, (size_t)BD * sizeof(float), cudaMemcpyDeviceToDevice, 0);

    ktrans_h<<<dim3(HID / 32, DIM / 32), dim3(32, 8)>>>(W1, W1p, DIM, HID);
    ktrans_h<<<dim3(DIM / 32, HID / 32), dim3(32, 8)>>>(W2, W2p, HID, DIM);
    ky<<<BD / 256, 256>>>(y_init, Yh, BD);

    // fork: quarter q on stream q (q=0 -> default stream)
    cudaEventRecord(evFork, 0);
    for (int i = 0; i < 3; ++i) cudaStreamWaitEvent(sx[i], evFork, 0);

    const dim3 g1(HID / 128, QROWS / 128);      // (32, 2) = 64 CTAs
    const dim3 g2(DIM / 128, QROWS / 128, 4);   // (8, 2, 4) = 64 CTAs
    const int RB = (QROWS * DIM) / 1024;        // 256 reduce blocks

    cudaStream_t strm[4] = {0, sx[0], sx[1], sx[2]};

    for (int s = 0; s < TSTEPS - 1; ++s) {
        const float* y = traj + (size_t)s * BD;
        float* ynext = traj + (size_t)(s + 1) * BD;

        for (int e = 1; e <= 4; ++e) {
            const float* yb = (e == 4) ? nullptr : y;
            float* yo = (e == 4) ? ynext : nullptr;
            for (int q = 0; q < 4; ++q) {
                const int roff = q * QROWS;
                cudaStream_t st = strm[q];
                hgemm1<<<g1, 128, SMEM, st>>>(Yh, W1p, b1, H, roff);
                hgemm2<<<g2, 128, SMEM, st>>>(H, W2p, P, roff);
                switch (e) {
                    case 1: kreduce<1><<<RB, 256, 0, st>>>(P, b2, yb, Yacc, yo, Yh, tspan, s, roff); break;
                    case 2: kreduce<2><<<RB, 256, 0, st>>>(P, b2, yb, Yacc, yo, Yh, tspan, s, roff); break;
                    case 3: kreduce<3><<<RB, 256, 0, st>>>(P, b2, yb, Yacc, yo, Yh, tspan, s, roff); break;
                    default: kreduce<4><<<RB, 256, 0, st>>>(P, b2, yb, Yacc, yo, Yh, tspan, s, roff); break;
                }
            }
        }
    }

    // join
    for (int i = 0; i < 3; ++i) {
        cudaEventRecord(evJoin[i], sx[i]);
        cudaStreamWaitEvent(0, evJoin[i], 0);
    }
}